// round 1
// baseline (speedup 1.0000x reference)
#include <cuda_runtime.h>
#include <stdint.h>

// Problem constants (from reference): NX=432, NY=496, C=64, B=4, P=40000
#define NXc 432
#define NYc 496
#define Bc 4
#define Cc 64
#define Pc 40000
#define PLANE (NYc * NXc)      // 214272 spatial positions per batch
#define NF (PLANE / 4)         // 53568 float4s per (b,c) plane (exact)
#define MAPSZ (Bc * PLANE)     // 857088

// Scratch: inverse map grid-cell -> pillar index (-1 = empty).
// Re-initialized every call (deterministic, graph-capturable, no allocs).
__device__ __align__(16) int g_map[MAPSZ];
__device__ int g_is_i64;

// Detect whether voxel_coords is int64 or int32 on device.
// Only inspect the first 10000 entries: 10000*3*8 = 240000 bytes, which is
// within the buffer even if it is actually int32 (120000*4 = 480000 bytes).
// int32 data misread as int64 yields values like (x | y<<32) -> out of range.
__global__ void detect_kernel(const long long* __restrict__ c) {
    __shared__ int bad;
    if (threadIdx.x == 0) bad = 0;
    __syncthreads();
    for (int i = threadIdx.x; i < 10000; i += blockDim.x) {
        long long x = c[3 * i + 0];
        long long y = c[3 * i + 1];
        long long b = c[3 * i + 2];
        if (x < 0 || x >= NXc || y < 0 || y >= NYc || b < 0 || b >= Bc) {
            bad = 1;
            break;
        }
        if (bad) break;
    }
    __syncthreads();
    if (threadIdx.x == 0) g_is_i64 = !bad;
}

__global__ void clear_map_kernel() {
    const int n = MAPSZ / 4;
    int4 v = make_int4(-1, -1, -1, -1);
    int4* m = reinterpret_cast<int4*>(g_map);
    for (int i = blockIdx.x * blockDim.x + threadIdx.x; i < n;
         i += gridDim.x * blockDim.x) {
        m[i] = v;
    }
}

__global__ void build_map_kernel(const void* __restrict__ coords) {
    int i = blockIdx.x * blockDim.x + threadIdx.x;
    if (i >= Pc) return;
    int x, y, b;
    if (g_is_i64) {
        const long long* c = (const long long*)coords;
        x = (int)c[3 * i + 0];
        y = (int)c[3 * i + 1];
        b = (int)c[3 * i + 2];
    } else {
        const int* c = (const int*)coords;
        x = c[3 * i + 0];
        y = c[3 * i + 1];
        b = c[3 * i + 2];
    }
    if ((unsigned)x < NXc && (unsigned)y < NYc && (unsigned)b < Bc) {
        g_map[b * PLANE + y * NXc + x] = i;
    }
}

// One thread owns one float4 of the (y,x) plane for one batch b.
// Reads 4 map entries once into registers, then writes all 64 channel planes
// with coalesced float4 streaming stores. Feature gathers: each pillar's 64
// floats (256B) are read contiguously by a single thread across the c-loop.
__global__ void __launch_bounds__(256) scatter_kernel(
    const float* __restrict__ feat, float* __restrict__ out) {
    int f = blockIdx.x * blockDim.x + threadIdx.x;  // float4 index in plane
    if (f >= NF) return;
    int b = blockIdx.y;

    int4 p4 = reinterpret_cast<const int4*>(g_map)[b * NF + f];

    float* ob = out + (size_t)b * Cc * PLANE + 4 * (size_t)f;
    const float* fx = feat + (size_t)p4.x * Cc;
    const float* fy = feat + (size_t)p4.y * Cc;
    const float* fz = feat + (size_t)p4.z * Cc;
    const float* fw = feat + (size_t)p4.w * Cc;

#pragma unroll 8
    for (int c = 0; c < Cc; ++c) {
        float4 v;
        v.x = (p4.x >= 0) ? __ldg(fx + c) : 0.0f;
        v.y = (p4.y >= 0) ? __ldg(fy + c) : 0.0f;
        v.z = (p4.z >= 0) ? __ldg(fz + c) : 0.0f;
        v.w = (p4.w >= 0) ? __ldg(fw + c) : 0.0f;
        __stcs(reinterpret_cast<float4*>(ob + (size_t)c * PLANE), v);
    }
}

extern "C" void kernel_launch(void* const* d_in, const int* in_sizes, int n_in,
                              void* d_out, int out_size) {
    const float* feat = (const float*)d_in[0];
    const void* coords = d_in[1];
    float* out = (float*)d_out;

    detect_kernel<<<1, 1024>>>((const long long*)coords);
    clear_map_kernel<<<512, 256>>>();
    build_map_kernel<<<(Pc + 255) / 256, 256>>>(coords);

    dim3 grid((NF + 255) / 256, Bc);
    scatter_kernel<<<grid, 256>>>(feat, out);
}

// round 3
// speedup vs baseline: 1.1396x; 1.1396x over previous
#include <cuda_runtime.h>
#include <stdint.h>

// Problem constants: NX=432, NY=496, C=64, B=4, P=40000
#define NXc 432
#define NYc 496
#define Bc 4
#define Cc 64
#define Pc 40000
#define PLANE (NYc * NXc)      // 214272
#define NF (PLANE / 4)         // 53568 float4s per plane (exact)
#define MAPSZ (Bc * PLANE)     // 857088
#define CPT 16                 // channels per thread
#define ZDIM (Cc / CPT)        // 4

// Scratch: inverse map cell -> pillar index (-1 = empty). Re-cleared each call.
__device__ __align__(16) int g_map[MAPSZ];
__device__ int g_is_i64;

// Block 0: dtype detection (int64 vs int32 coords). Other blocks: clear map.
// Detection reads only the first 10000 entries as i64 (240KB) which is within
// the buffer even if it is int32 (480KB). int32 misread as i64 -> out of range.
__global__ void prep_kernel(const long long* __restrict__ c) {
    if (blockIdx.x == 0) {
        __shared__ int bad;
        if (threadIdx.x == 0) bad = 0;
        __syncthreads();
        for (int i = threadIdx.x; i < 10000; i += blockDim.x) {
            long long x = c[3 * i + 0];
            long long y = c[3 * i + 1];
            long long b = c[3 * i + 2];
            if (x < 0 || x >= NXc || y < 0 || y >= NYc || b < 0 || b >= Bc) {
                bad = 1;
                break;
            }
            if (bad) break;
        }
        __syncthreads();
        if (threadIdx.x == 0) g_is_i64 = !bad;
    }
    // All blocks (including 0) participate in clearing the map.
    const int n = MAPSZ / 4;
    int4 v = make_int4(-1, -1, -1, -1);
    int4* m = reinterpret_cast<int4*>(g_map);
    for (int i = blockIdx.x * blockDim.x + threadIdx.x; i < n;
         i += gridDim.x * blockDim.x) {
        m[i] = v;
    }
}

__global__ void build_map_kernel(const void* __restrict__ coords) {
    int i = blockIdx.x * blockDim.x + threadIdx.x;
    if (i >= Pc) return;
    int x, y, b;
    if (g_is_i64) {
        const long long* c = (const long long*)coords;
        x = (int)c[3 * i + 0];
        y = (int)c[3 * i + 1];
        b = (int)c[3 * i + 2];
    } else {
        const int* c = (const int*)coords;
        x = c[3 * i + 0];
        y = c[3 * i + 1];
        b = c[3 * i + 2];
    }
    if ((unsigned)x < NXc && (unsigned)y < NYc && (unsigned)b < Bc) {
        g_map[b * PLANE + y * NXc + x] = i;
    }
}

// Thread owns one float4 of the (y,x) plane for batch b, channels
// [c0, c0+CPT). Loads map int4 once; per 4-channel chunk: 4 independent
// float4 feature gathers (16B each, sector-friendly) -> register transpose
// -> 4 coalesced float4 streaming plane stores.
__global__ void __launch_bounds__(256) scatter_kernel(
    const float* __restrict__ feat, float* __restrict__ out) {
    int f = blockIdx.x * blockDim.x + threadIdx.x;
    if (f >= NF) return;
    int b = blockIdx.y;
    int c0 = blockIdx.z * CPT;

    int4 p4 = reinterpret_cast<const int4*>(g_map)[b * NF + f];

    float* ob = out + ((size_t)b * Cc + c0) * PLANE + 4 * (size_t)f;
    const float4* fx = reinterpret_cast<const float4*>(feat + (size_t)p4.x * Cc + c0);
    const float4* fy = reinterpret_cast<const float4*>(feat + (size_t)p4.y * Cc + c0);
    const float4* fz = reinterpret_cast<const float4*>(feat + (size_t)p4.z * Cc + c0);
    const float4* fw = reinterpret_cast<const float4*>(feat + (size_t)p4.w * Cc + c0);

    const float4 zero = make_float4(0.f, 0.f, 0.f, 0.f);

#pragma unroll
    for (int k = 0; k < CPT / 4; ++k) {
        float4 A = (p4.x >= 0) ? __ldg(fx + k) : zero;
        float4 B = (p4.y >= 0) ? __ldg(fy + k) : zero;
        float4 C = (p4.z >= 0) ? __ldg(fz + k) : zero;
        float4 D = (p4.w >= 0) ? __ldg(fw + k) : zero;

        float4* o = reinterpret_cast<float4*>(ob + (size_t)(4 * k) * PLANE);
        __stcs(o, make_float4(A.x, B.x, C.x, D.x));
        o = reinterpret_cast<float4*>(ob + (size_t)(4 * k + 1) * PLANE);
        __stcs(o, make_float4(A.y, B.y, C.y, D.y));
        o = reinterpret_cast<float4*>(ob + (size_t)(4 * k + 2) * PLANE);
        __stcs(o, make_float4(A.z, B.z, C.z, D.z));
        o = reinterpret_cast<float4*>(ob + (size_t)(4 * k + 3) * PLANE);
        __stcs(o, make_float4(A.w, B.w, C.w, D.w));
    }
}

extern "C" void kernel_launch(void* const* d_in, const int* in_sizes, int n_in,
                              void* d_out, int out_size) {
    const float* feat = (const float*)d_in[0];
    const void* coords = d_in[1];
    float* out = (float*)d_out;

    prep_kernel<<<512, 256>>>((const long long*)coords);
    build_map_kernel<<<(Pc + 255) / 256, 256>>>(coords);

    dim3 grid((NF + 255) / 256, Bc, ZDIM);
    scatter_kernel<<<grid, 256>>>(feat, out);
}

// round 4
// speedup vs baseline: 1.1555x; 1.0139x over previous
#include <cuda_runtime.h>
#include <stdint.h>

// Problem constants: NX=432, NY=496, C=64, B=4, P=40000
#define NXc 432
#define NYc 496
#define Bc 4
#define Cc 64
#define Pc 40000
#define PLANE (NYc * NXc)      // 214272
#define NF (PLANE / 4)         // 53568 float4s per plane (exact)
#define MAPSZ (Bc * PLANE)     // 857088
#define CPT 16                 // channels per thread
#define ZDIM (Cc / CPT)        // 4

// Scratch: inverse map cell -> pillar index (-1 = empty). Re-cleared each call.
__device__ __align__(16) int g_map[MAPSZ];
__device__ int g_is_i64;

// Clear the map with a wide grid; warp 0 of block 0 additionally detects the
// coords dtype (int64 vs int32) from just 32 entries. For int32 data misread
// as i64 to pass ONE entry's range check, three specific int32 words must all
// be zero (p ~ 1e-6); all 32 passing is impossible. 32 entries * 24B = 768B,
// within the buffer under either dtype.
__global__ void prep_kernel(const long long* __restrict__ c) {
    if (blockIdx.x == 0 && threadIdx.x < 32) {
        int lane = threadIdx.x;
        long long x = c[3 * lane + 0];
        long long y = c[3 * lane + 1];
        long long b = c[3 * lane + 2];
        bool ok = (x >= 0 && x < NXc && y >= 0 && y < NYc && b >= 0 && b < Bc);
        unsigned all_ok = __ballot_sync(0xFFFFFFFFu, ok);
        if (lane == 0) g_is_i64 = (all_ok == 0xFFFFFFFFu) ? 1 : 0;
    }
    // All blocks clear the map (int4 stores, <=1 per thread).
    const int n = MAPSZ / 4;  // 214272
    int i = blockIdx.x * blockDim.x + threadIdx.x;
    int4* m = reinterpret_cast<int4*>(g_map);
    if (i < n) m[i] = make_int4(-1, -1, -1, -1);
}

__global__ void build_map_kernel(const void* __restrict__ coords) {
    int i = blockIdx.x * blockDim.x + threadIdx.x;
    if (i >= Pc) return;
    int x, y, b;
    if (g_is_i64) {
        const long long* c = (const long long*)coords;
        x = (int)c[3 * i + 0];
        y = (int)c[3 * i + 1];
        b = (int)c[3 * i + 2];
    } else {
        const int* c = (const int*)coords;
        x = c[3 * i + 0];
        y = c[3 * i + 1];
        b = c[3 * i + 2];
    }
    if ((unsigned)x < NXc && (unsigned)y < NYc && (unsigned)b < Bc) {
        g_map[b * PLANE + y * NXc + x] = i;
    }
}

// Thread owns one float4 of the (y,x) plane for batch b, channels
// [c0, c0+CPT). Loads map int4 once; per 4-channel chunk: 4 independent
// float4 feature gathers (16B each, sector-friendly) -> register transpose
// -> 4 coalesced float4 streaming plane stores.
__global__ void __launch_bounds__(256) scatter_kernel(
    const float* __restrict__ feat, float* __restrict__ out) {
    int f = blockIdx.x * blockDim.x + threadIdx.x;
    if (f >= NF) return;
    int b = blockIdx.y;
    int c0 = blockIdx.z * CPT;

    int4 p4 = __ldg(reinterpret_cast<const int4*>(g_map) + b * NF + f);

    float* ob = out + ((size_t)b * Cc + c0) * PLANE + 4 * (size_t)f;
    const float4* fx = reinterpret_cast<const float4*>(feat + (size_t)p4.x * Cc + c0);
    const float4* fy = reinterpret_cast<const float4*>(feat + (size_t)p4.y * Cc + c0);
    const float4* fz = reinterpret_cast<const float4*>(feat + (size_t)p4.z * Cc + c0);
    const float4* fw = reinterpret_cast<const float4*>(feat + (size_t)p4.w * Cc + c0);

    const float4 zero = make_float4(0.f, 0.f, 0.f, 0.f);

#pragma unroll
    for (int k = 0; k < CPT / 4; ++k) {
        float4 A = (p4.x >= 0) ? __ldg(fx + k) : zero;
        float4 B = (p4.y >= 0) ? __ldg(fy + k) : zero;
        float4 C = (p4.z >= 0) ? __ldg(fz + k) : zero;
        float4 D = (p4.w >= 0) ? __ldg(fw + k) : zero;

        float4* o = reinterpret_cast<float4*>(ob + (size_t)(4 * k) * PLANE);
        __stcs(o, make_float4(A.x, B.x, C.x, D.x));
        o = reinterpret_cast<float4*>(ob + (size_t)(4 * k + 1) * PLANE);
        __stcs(o, make_float4(A.y, B.y, C.y, D.y));
        o = reinterpret_cast<float4*>(ob + (size_t)(4 * k + 2) * PLANE);
        __stcs(o, make_float4(A.z, B.z, C.z, D.z));
        o = reinterpret_cast<float4*>(ob + (size_t)(4 * k + 3) * PLANE);
        __stcs(o, make_float4(A.w, B.w, C.w, D.w));
    }
}

extern "C" void kernel_launch(void* const* d_in, const int* in_sizes, int n_in,
                              void* d_out, int out_size) {
    const float* feat = (const float*)d_in[0];
    const void* coords = d_in[1];
    float* out = (float*)d_out;

    prep_kernel<<<(MAPSZ / 4 + 255) / 256, 256>>>((const long long*)coords);
    build_map_kernel<<<(Pc + 255) / 256, 256>>>(coords);

    dim3 grid((NF + 255) / 256, Bc, ZDIM);
    scatter_kernel<<<grid, 256>>>(feat, out);
}